// round 7
// baseline (speedup 1.0000x reference)
#include <cuda_runtime.h>
#include <cstdint>

// CSR SpMM, sum-reduce: out[r,:] = sum_e value[e] * other[col[e],:]
// N_ROWS=100000, DEG=16 (fixed), F=64, fp32. rowptr/col INT32.
//
// R3-R5 plateaued at ~27us across occ 32-87%: binding constraint is L1tex
// wavefront REPLAY rate, not L2 (imputed L2-saturated time ~17.5us) and not
// occupancy. Old shape: LDG.E.128, warp=512B over 4 lines -> 4 within-LDG
// wavefronts @2.07cyc each -> ~3.6 cyc/256B. New shape: ONE WARP PER ROW,
// lane L loads float2 -> LDG.E.64 covers the whole 256B row in 2 lines ->
// ~3.07 cyc/256B AND halves LDG count vs a float2 2-row scheme.
// Gather cost/SM ~16.6us == LSU issue ~16us == L2 roofline ~17.5us: balanced.
//
// blockDim=256 (8 warps = 8 rows/block). Metadata via broadcast int4/float4
// loads (1 line each). Gathers in two batches of 8 for MLP.

static constexpr int WARPS_PER_BLK = 8;

__global__ __launch_bounds__(256, 4) void spmm_kernel(
    const int* __restrict__ rowptr,
    const int* __restrict__ col,
    const float* __restrict__ value,
    const float2* __restrict__ other,   // [N_COLS * 32] float2
    float2* __restrict__ out,           // [N_ROWS * 32] float2
    int n_rows)
{
    const int warp = threadIdx.x >> 5;
    const int lane = threadIdx.x & 31;
    const int row  = blockIdx.x * WARPS_PER_BLK + warp;
    if (row >= n_rows) return;

    const int start = rowptr[row];
    const int deg   = rowptr[row + 1] - start;

    float2 acc = make_float2(0.f, 0.f);

    if (deg == 16 && (start & 3) == 0) {
        // Broadcast metadata: all lanes load the same int4/float4 (1 line, 1 wf each).
        const int4*   c4 = (const int4*)(col + start);
        const float4* v4 = (const float4*)(value + start);
        int4   c[4];
        float4 v[4];
#pragma unroll
        for (int b = 0; b < 4; ++b) {
            c[b] = __ldg(&c4[b]);
            v[b] = __ldg(&v4[b]);
        }

        // Two batches of 8 independent full-row gathers (LDG.E.64, 2 lines each).
#pragma unroll
        for (int h = 0; h < 2; ++h) {
            const int4   ca = c[2 * h + 0];
            const int4   cb = c[2 * h + 1];
            const float4 va = v[2 * h + 0];
            const float4 vb = v[2 * h + 1];

            float2 x0 = __ldg(&other[(long long)ca.x * 32 + lane]);
            float2 x1 = __ldg(&other[(long long)ca.y * 32 + lane]);
            float2 x2 = __ldg(&other[(long long)ca.z * 32 + lane]);
            float2 x3 = __ldg(&other[(long long)ca.w * 32 + lane]);
            float2 x4 = __ldg(&other[(long long)cb.x * 32 + lane]);
            float2 x5 = __ldg(&other[(long long)cb.y * 32 + lane]);
            float2 x6 = __ldg(&other[(long long)cb.z * 32 + lane]);
            float2 x7 = __ldg(&other[(long long)cb.w * 32 + lane]);

            acc.x = fmaf(va.x, x0.x, acc.x);  acc.y = fmaf(va.x, x0.y, acc.y);
            acc.x = fmaf(va.y, x1.x, acc.x);  acc.y = fmaf(va.y, x1.y, acc.y);
            acc.x = fmaf(va.z, x2.x, acc.x);  acc.y = fmaf(va.z, x2.y, acc.y);
            acc.x = fmaf(va.w, x3.x, acc.x);  acc.y = fmaf(va.w, x3.y, acc.y);
            acc.x = fmaf(vb.x, x4.x, acc.x);  acc.y = fmaf(vb.x, x4.y, acc.y);
            acc.x = fmaf(vb.y, x5.x, acc.x);  acc.y = fmaf(vb.y, x5.y, acc.y);
            acc.x = fmaf(vb.z, x6.x, acc.x);  acc.y = fmaf(vb.z, x6.y, acc.y);
            acc.x = fmaf(vb.w, x7.x, acc.x);  acc.y = fmaf(vb.w, x7.y, acc.y);
        }
    } else {
        for (int e = start; e < start + deg; ++e) {
            const int   cc = __ldg(&col[e]);
            const float vv = __ldg(&value[e]);
            const float2 x = __ldg(&other[(long long)cc * 32 + lane]);
            acc.x = fmaf(vv, x.x, acc.x);
            acc.y = fmaf(vv, x.y, acc.y);
        }
    }

    out[(long long)row * 32 + lane] = acc;
}

extern "C" void kernel_launch(void* const* d_in, const int* in_sizes, int n_in,
                              void* d_out, int out_size)
{
    // metadata order: rowptr (int32, N_ROWS+1), col (int32, E), value (f32, E), other (f32, N_COLS*F)
    const int*    rowptr = (const int*)d_in[0];
    const int*    col    = (const int*)d_in[1];
    const float*  value  = (const float*)d_in[2];
    const float2* other  = (const float2*)d_in[3];
    float2*       out    = (float2*)d_out;

    const int n_rows = in_sizes[0] - 1;

    dim3 block(WARPS_PER_BLK * 32);
    dim3 grid((n_rows + WARPS_PER_BLK - 1) / WARPS_PER_BLK);
    spmm_kernel<<<grid, block>>>(rowptr, col, value, other, out, n_rows);
}

// round 10
// speedup vs baseline: 1.3778x; 1.3778x over previous
#include <cuda_runtime.h>
#include <cstdint>

// CSR SpMM, sum-reduce: out[r,:] = sum_e value[e] * other[col[e],:]
// N_ROWS=100000, DEG=16 (fixed), F=64, fp32. rowptr/col INT32.
//
// Limiter analysis (R3-R6): L2% x dur == 17.5us for ALL designs -> L2 never
// saturated; limiter is per-SM gather concurrency. Best results track
// (warps/SM x gathers-in-flight). R7 = R5's winning shape (16 lanes/row,
// LDG.E.128 gathers, vectorized broadcast metadata) pushed to 6 CTAs/SM:
//  - metadata loaded just-in-time per 4-edge batch (cuts live regs to ~40)
//  - __launch_bounds__(256,6): 48 warps/SM x MLP~4 = ~192 gathers in flight
//  - gathers use __ldcg (L2-only): ~0% L1 hit rate, skip L1 fill overhead

static constexpr int F4 = 16;       // float4 groups per row (F=64)
static constexpr int ROWS_PER_BLK = 16;

__global__ __launch_bounds__(256, 6) void spmm_kernel(
    const int* __restrict__ rowptr,
    const int* __restrict__ col,
    const float* __restrict__ value,
    const float4* __restrict__ other,   // [N_COLS * 16] float4
    float4* __restrict__ out,           // [N_ROWS * 16] float4
    int n_rows)
{
    const int row = blockIdx.x * ROWS_PER_BLK + threadIdx.y;
    if (row >= n_rows) return;
    const int f = threadIdx.x;          // 0..15

    const int start = rowptr[row];
    const int deg   = rowptr[row + 1] - start;

    float4 acc = make_float4(0.f, 0.f, 0.f, 0.f);

    if (deg == 16 && (start & 3) == 0) {
        const int4*   c4 = (const int4*)(col + start);
        const float4* v4 = (const float4*)(value + start);

        // 4 batches of 4 edges. Metadata (one int4 + one float4, broadcast
        // within the 16-lane row group) loaded just-in-time; 4 independent
        // LDG.E.128 gathers in flight per batch, adjacent batches overlap.
#pragma unroll
        for (int b = 0; b < 4; ++b) {
            const int4   c = __ldg(&c4[b]);
            const float4 v = __ldg(&v4[b]);

            float4 x0 = __ldcg(&other[(long long)c.x * F4 + f]);
            float4 x1 = __ldcg(&other[(long long)c.y * F4 + f]);
            float4 x2 = __ldcg(&other[(long long)c.z * F4 + f]);
            float4 x3 = __ldcg(&other[(long long)c.w * F4 + f]);

            acc.x = fmaf(v.x, x0.x, acc.x);
            acc.y = fmaf(v.x, x0.y, acc.y);
            acc.z = fmaf(v.x, x0.z, acc.z);
            acc.w = fmaf(v.x, x0.w, acc.w);

            acc.x = fmaf(v.y, x1.x, acc.x);
            acc.y = fmaf(v.y, x1.y, acc.y);
            acc.z = fmaf(v.y, x1.z, acc.z);
            acc.w = fmaf(v.y, x1.w, acc.w);

            acc.x = fmaf(v.z, x2.x, acc.x);
            acc.y = fmaf(v.z, x2.y, acc.y);
            acc.z = fmaf(v.z, x2.z, acc.z);
            acc.w = fmaf(v.z, x2.w, acc.w);

            acc.x = fmaf(v.w, x3.x, acc.x);
            acc.y = fmaf(v.w, x3.y, acc.y);
            acc.z = fmaf(v.w, x3.z, acc.z);
            acc.w = fmaf(v.w, x3.w, acc.w);
        }
    } else {
        for (int e = start; e < start + deg; ++e) {
            const int   c = __ldg(&col[e]);
            const float v = __ldg(&value[e]);
            const float4 x = __ldcg(&other[(long long)c * F4 + f]);
            acc.x = fmaf(v, x.x, acc.x);
            acc.y = fmaf(v, x.y, acc.y);
            acc.z = fmaf(v, x.z, acc.z);
            acc.w = fmaf(v, x.w, acc.w);
        }
    }

    out[(long long)row * F4 + f] = acc;
}

extern "C" void kernel_launch(void* const* d_in, const int* in_sizes, int n_in,
                              void* d_out, int out_size)
{
    // metadata order: rowptr (int32, N_ROWS+1), col (int32, E), value (f32, E), other (f32, N_COLS*F)
    const int*    rowptr = (const int*)d_in[0];
    const int*    col    = (const int*)d_in[1];
    const float*  value  = (const float*)d_in[2];
    const float4* other  = (const float4*)d_in[3];
    float4*       out    = (float4*)d_out;

    const int n_rows = in_sizes[0] - 1;

    dim3 block(F4, ROWS_PER_BLK);
    dim3 grid((n_rows + ROWS_PER_BLK - 1) / ROWS_PER_BLK);
    spmm_kernel<<<grid, block>>>(rowptr, col, value, other, out, n_rows);
}